// round 1
// baseline (speedup 1.0000x reference)
#include <cuda_runtime.h>

#define HH 512
#define WW 512
#define OW 506
#define BATCH 32
#define CH 3
#define TILE 32
#define IT 38   // TILE + 6 (input tile for valid 7x7)

__device__ unsigned g_minBits[BATCH];
__device__ unsigned g_maxBits[BATCH];
__device__ double g_acc;

__global__ void init_kernel() {
    int t = threadIdx.x;
    if (t == 0) g_acc = 0.0;
    if (t < BATCH) { g_minBits[t] = 0xFFFFFFFFu; g_maxBits[t] = 0u; }
}

// Per-image min/max of img2. Values are uniform[0,1) (non-negative), so the
// uint bit pattern ordering equals float ordering.
__global__ void minmax_kernel(const float* __restrict__ img2) {
    int b = blockIdx.x;
    const float4* p = (const float4*)(img2 + (size_t)b * (CH * HH * WW));
    const int n4 = CH * HH * WW / 4;
    unsigned lo = 0xFFFFFFFFu, hi = 0u;
    for (int i = blockIdx.y * blockDim.x + threadIdx.x; i < n4;
         i += gridDim.y * blockDim.x) {
        float4 v = p[i];
        unsigned a0 = __float_as_uint(v.x), a1 = __float_as_uint(v.y);
        unsigned a2 = __float_as_uint(v.z), a3 = __float_as_uint(v.w);
        lo = min(lo, min(min(a0, a1), min(a2, a3)));
        hi = max(hi, max(max(a0, a1), max(a2, a3)));
    }
    #pragma unroll
    for (int o = 16; o; o >>= 1) {
        lo = min(lo, __shfl_down_sync(0xffffffffu, lo, o));
        hi = max(hi, __shfl_down_sync(0xffffffffu, hi, o));
    }
    __shared__ unsigned slo[8], shi[8];
    int lane = threadIdx.x & 31, w = threadIdx.x >> 5;
    if (lane == 0) { slo[w] = lo; shi[w] = hi; }
    __syncthreads();
    if (threadIdx.x == 0) {
        int nw = blockDim.x >> 5;
        for (int i = 1; i < nw; i++) { lo = min(lo, slo[i]); hi = max(hi, shi[i]); }
        atomicMin(&g_minBits[b], lo);
        atomicMax(&g_maxBits[b], hi);
    }
}

// Fused SSIM: per block, one 32x32 output tile of one (b,c) map.
// Separable 7x7 box sums: horizontal running sums into SMEM, vertical
// running sums in registers, SSIM formula, block reduction, one double atomic.
__global__ __launch_bounds__(256) void ssim_kernel(const float* __restrict__ X,
                                                   const float* __restrict__ Y) {
    __shared__ float sx[IT][39];       // stride 39 (odd) -> conflict-free
    __shared__ float sy[IT][39];
    __shared__ float hs[5][IT][33];    // stride 33 -> conflict-free
    __shared__ float wsum[8];

    const int z = blockIdx.z;                 // b*3 + c
    const size_t base = (size_t)z * (HH * WW);
    const int x0 = blockIdx.x * TILE;
    const int y0 = blockIdx.y * TILE;
    const int tid = threadIdx.x, lane = tid & 31, warp = tid >> 5;

    // ---- stage 1: load 38x38 input tiles (zero-padded OOB, masked later) ----
    for (int r = warp; r < IT; r += 8) {
        const int iy = y0 + r;
        const bool yok = iy < HH;
        const float* px = X + base + (size_t)iy * WW;
        const float* py = Y + base + (size_t)iy * WW;
        int c = lane, ix = x0 + c;
        bool ok = yok && (ix < WW);
        sx[r][c] = ok ? px[ix] : 0.f;
        sy[r][c] = ok ? py[ix] : 0.f;
        if (lane < IT - 32) {
            c = lane + 32; ix = x0 + c;
            ok = yok && (ix < WW);
            sx[r][c] = ok ? px[ix] : 0.f;
            sy[r][c] = ok ? py[ix] : 0.f;
        }
    }
    __syncthreads();

    // ---- stage 2: horizontal 7-sums (running), 4 output cols per item ----
    for (int item = tid; item < IT * 8; item += 256) {
        const int r = item >> 3;
        const int c0 = (item & 7) * 4;
        float s1 = 0.f, s2 = 0.f, s3 = 0.f, s4 = 0.f, s5 = 0.f;
        #pragma unroll
        for (int k = 0; k < 7; k++) {
            float vx = sx[r][c0 + k], vy = sy[r][c0 + k];
            s1 += vx; s2 += vy;
            s3 += vx * vx; s4 += vy * vy; s5 += vx * vy;
        }
        hs[0][r][c0] = s1; hs[1][r][c0] = s2; hs[2][r][c0] = s3;
        hs[3][r][c0] = s4; hs[4][r][c0] = s5;
        #pragma unroll
        for (int j = 1; j < 4; j++) {
            float vxn = sx[r][c0 + 6 + j], vyn = sy[r][c0 + 6 + j];
            float vxo = sx[r][c0 + j - 1], vyo = sy[r][c0 + j - 1];
            s1 += vxn - vxo;
            s2 += vyn - vyo;
            s3 += vxn * vxn - vxo * vxo;
            s4 += vyn * vyn - vyo * vyo;
            s5 += vxn * vyn - vxo * vyo;
            hs[0][r][c0 + j] = s1; hs[1][r][c0 + j] = s2; hs[2][r][c0 + j] = s3;
            hs[3][r][c0 + j] = s4; hs[4][r][c0 + j] = s5;
        }
    }
    __syncthreads();

    // per-image constants
    const int b = z / CH;
    const float dr = __uint_as_float(g_maxBits[b]) - __uint_as_float(g_minBits[b]);
    const float C1 = (0.01f * dr) * (0.01f * dr);
    const float C2 = (0.03f * dr) * (0.03f * dr);

    // ---- stage 3: vertical 7-sums (running) + SSIM; 4 rows per thread ----
    const int c = lane;
    const int r0 = warp * 4;
    float t1 = 0.f, t2 = 0.f, t3 = 0.f, t4 = 0.f, t5 = 0.f;
    #pragma unroll
    for (int k = 0; k < 7; k++) {
        t1 += hs[0][r0 + k][c]; t2 += hs[1][r0 + k][c]; t3 += hs[2][r0 + k][c];
        t4 += hs[3][r0 + k][c]; t5 += hs[4][r0 + k][c];
    }
    float accS = 0.f;
    const float inv = 1.f / 49.f;
    const float covn = 49.f / 48.f;
    const int ox = x0 + c;
    #pragma unroll
    for (int j = 0; j < 4; j++) {
        if (j > 0) {
            t1 += hs[0][r0 + 6 + j][c] - hs[0][r0 + j - 1][c];
            t2 += hs[1][r0 + 6 + j][c] - hs[1][r0 + j - 1][c];
            t3 += hs[2][r0 + 6 + j][c] - hs[2][r0 + j - 1][c];
            t4 += hs[3][r0 + 6 + j][c] - hs[3][r0 + j - 1][c];
            t5 += hs[4][r0 + 6 + j][c] - hs[4][r0 + j - 1][c];
        }
        const int oy = y0 + r0 + j;
        if (ox < OW && oy < OW) {
            float ux = t1 * inv, uy = t2 * inv;
            float uxx = t3 * inv, uyy = t4 * inv, uxy = t5 * inv;
            float vx = covn * (uxx - ux * ux);
            float vy = covn * (uyy - uy * uy);
            float vxy = covn * (uxy - ux * uy);
            float A1 = 2.f * ux * uy + C1;
            float A2 = 2.f * vxy + C2;
            float B1 = ux * ux + uy * uy + C1;
            float B2 = vx + vy + C2;
            accS += (A1 * A2) / (B1 * B2);
        }
    }

    // ---- block reduction -> one double atomic ----
    #pragma unroll
    for (int o = 16; o; o >>= 1) accS += __shfl_down_sync(0xffffffffu, accS, o);
    if (lane == 0) wsum[warp] = accS;
    __syncthreads();
    if (tid == 0) {
        float s = 0.f;
        #pragma unroll
        for (int i = 0; i < 8; i++) s += wsum[i];
        atomicAdd(&g_acc, (double)s);
    }
}

__global__ void finalize_kernel(float* out) {
    out[0] = (float)(1.0 - g_acc / ((double)BATCH * CH * OW * OW));
}

extern "C" void kernel_launch(void* const* d_in, const int* in_sizes, int n_in,
                              void* d_out, int out_size) {
    const float* img1 = (const float*)d_in[0];
    const float* img2 = (const float*)d_in[1];

    init_kernel<<<1, 64>>>();
    minmax_kernel<<<dim3(BATCH, 16), 256>>>(img2);
    dim3 grid((OW + TILE - 1) / TILE, (OW + TILE - 1) / TILE, BATCH * CH);
    ssim_kernel<<<grid, 256>>>(img1, img2);
    finalize_kernel<<<1, 1>>>((float*)d_out);
}